// round 5
// baseline (speedup 1.0000x reference)
#include <cuda_runtime.h>

#define BB 32
#define CC 256
#define TT 4096
#define NH 8
#define DH 64
#define DK 512   // NH*DH

// Scratch (allocation-free per harness rules)
__device__ float g_qW[BB * NH * CC];        // scale-folded q @ Wkv_k
__device__ float g_pl[4][BB * NH * TT];     // partial logits, 4 c-quarters
__device__ float g_attn[BB * NH * TT];      // softmax output
__device__ float g_xp[2][BB * NH * CC];     // xattn partials, 2 j-halves

// ---------------------------------------------------------------------------
// Kernel A: per (n,b): q[n,:] = query@Wq.T + bq ; qW[b,n,c] = scale * q·Wkv_k[:,c]
// grid = (8 n, 32 b), 256 threads
// ---------------------------------------------------------------------------
__global__ void k_prep(const float* __restrict__ query,
                       const float* __restrict__ Wq,
                       const float* __restrict__ bq,
                       const float* __restrict__ Wkv) {
    const int n = blockIdx.x, b = blockIdx.y;
    const int tid = threadIdx.x, wid = tid >> 5, lane = tid & 31;
    __shared__ float qin[CC];
    __shared__ float qs[DH];

    qin[tid] = query[b * CC + tid];
    __syncthreads();

    const float4* qv = (const float4*)qin;
    for (int d = wid; d < DH; d += 8) {
        const float4* wr = (const float4*)(Wq + (size_t)(n * DH + d) * CC);
        float s = 0.f;
#pragma unroll
        for (int i = 0; i < 2; ++i) {
            const float4 w = wr[lane + i * 32];
            const float4 q4 = qv[lane + i * 32];
            s += w.x * q4.x + w.y * q4.y + w.z * q4.z + w.w * q4.w;
        }
#pragma unroll
        for (int o = 16; o; o >>= 1) s += __shfl_xor_sync(~0u, s, o);
        if (!lane) qs[d] = s + bq[n * DH + d];
    }
    __syncthreads();

    const float* wbase = Wkv + (size_t)(n * DH) * CC + tid;
    float s = 0.f;
#pragma unroll 8
    for (int d = 0; d < DH; ++d) s += qs[d] * wbase[(size_t)d * CC];
    g_qW[(b * NH + n) * CC + tid] = s * 0.125f;  // 1/sqrt(64)
}

// ---------------------------------------------------------------------------
// Kernel B: partial logits, c split in quarters across blockIdx.y.
// grid = (8 j-tiles of 512, 4 c-quarters, 32 b), 128 threads.
// ---------------------------------------------------------------------------
__global__ void __launch_bounds__(128) k_logits(const float* __restrict__ x) {
    const int b = blockIdx.z;
    const int cq = blockIdx.y;                       // c quarter
    const int jq = blockIdx.x * 128 + threadIdx.x;   // float4 index into j

    __shared__ float4 qwT[64][2];                    // [c][n-quad], 512 floats
    for (int i = threadIdx.x; i < 64 * NH; i += 128) {
        const int c = i >> 3, n = i & 7;
        ((float*)&qwT[c][0])[n] = g_qW[(b * NH + n) * CC + cq * 64 + c];
    }
    __syncthreads();

    float4 acc[NH];
#pragma unroll
    for (int n = 0; n < NH; ++n) acc[n] = make_float4(0.f, 0.f, 0.f, 0.f);

    const float4* xp = (const float4*)(x + ((size_t)b * CC + cq * 64) * TT) + jq;
#pragma unroll 8
    for (int c = 0; c < 64; ++c) {
        const float4 xv = xp[(size_t)c * (TT / 4)];
        const float4 w0 = qwT[c][0];
        const float4 w1 = qwT[c][1];
        acc[0].x += w0.x * xv.x; acc[0].y += w0.x * xv.y; acc[0].z += w0.x * xv.z; acc[0].w += w0.x * xv.w;
        acc[1].x += w0.y * xv.x; acc[1].y += w0.y * xv.y; acc[1].z += w0.y * xv.z; acc[1].w += w0.y * xv.w;
        acc[2].x += w0.z * xv.x; acc[2].y += w0.z * xv.y; acc[2].z += w0.z * xv.z; acc[2].w += w0.z * xv.w;
        acc[3].x += w0.w * xv.x; acc[3].y += w0.w * xv.y; acc[3].z += w0.w * xv.z; acc[3].w += w0.w * xv.w;
        acc[4].x += w1.x * xv.x; acc[4].y += w1.x * xv.y; acc[4].z += w1.x * xv.z; acc[4].w += w1.x * xv.w;
        acc[5].x += w1.y * xv.x; acc[5].y += w1.y * xv.y; acc[5].z += w1.y * xv.z; acc[5].w += w1.y * xv.w;
        acc[6].x += w1.z * xv.x; acc[6].y += w1.z * xv.y; acc[6].z += w1.z * xv.z; acc[6].w += w1.z * xv.w;
        acc[7].x += w1.w * xv.x; acc[7].y += w1.w * xv.y; acc[7].z += w1.w * xv.z; acc[7].w += w1.w * xv.w;
    }

#pragma unroll
    for (int n = 0; n < NH; ++n)
        ((float4*)(g_pl[cq] + (size_t)(b * NH + n) * TT))[jq] = acc[n];
}

// ---------------------------------------------------------------------------
// Kernel C: logits = sum of 4 partials, softmax over j=4096.
// grid = 256 rows, 256 threads
// ---------------------------------------------------------------------------
__global__ void k_softmax() {
    const int row = blockIdx.x;
    const int tid = threadIdx.x;
    float4* pa = (float4*)(g_attn + (size_t)row * TT);

    float4 v[4];
#pragma unroll
    for (int i = 0; i < 4; ++i) {
        float4 a = ((const float4*)(g_pl[0] + (size_t)row * TT))[tid + i * 256];
#pragma unroll
        for (int p = 1; p < 4; ++p) {
            const float4 c = ((const float4*)(g_pl[p] + (size_t)row * TT))[tid + i * 256];
            a.x += c.x; a.y += c.y; a.z += c.z; a.w += c.w;
        }
        v[i] = a;
    }

    float m = -1e30f;
#pragma unroll
    for (int i = 0; i < 4; ++i)
        m = fmaxf(m, fmaxf(fmaxf(v[i].x, v[i].y), fmaxf(v[i].z, v[i].w)));

    __shared__ float red[8];
#pragma unroll
    for (int o = 16; o; o >>= 1) m = fmaxf(m, __shfl_xor_sync(~0u, m, o));
    if ((tid & 31) == 0) red[tid >> 5] = m;
    __syncthreads();
    m = red[0];
#pragma unroll
    for (int i = 1; i < 8; ++i) m = fmaxf(m, red[i]);
    __syncthreads();

    float s = 0.f;
#pragma unroll
    for (int i = 0; i < 4; ++i) {
        v[i].x = __expf(v[i].x - m); v[i].y = __expf(v[i].y - m);
        v[i].z = __expf(v[i].z - m); v[i].w = __expf(v[i].w - m);
        s += v[i].x + v[i].y + v[i].z + v[i].w;
    }
#pragma unroll
    for (int o = 16; o; o >>= 1) s += __shfl_xor_sync(~0u, s, o);
    if ((tid & 31) == 0) red[tid >> 5] = s;
    __syncthreads();
    s = red[0];
#pragma unroll
    for (int i = 1; i < 8; ++i) s += red[i];

    const float inv = 1.f / s;
#pragma unroll
    for (int i = 0; i < 4; ++i) {
        v[i].x *= inv; v[i].y *= inv; v[i].z *= inv; v[i].w *= inv;
        pa[tid + i * 256] = v[i];
    }
}

// ---------------------------------------------------------------------------
// Kernel D: xattn partial over j-half. grid = (16 c-tiles of 16, 2 jh, 32 b),
// 256 threads = 8 warps, warp owns 2 c. Unroll 4 j-steps -> 8 LDGs in flight.
// ---------------------------------------------------------------------------
__global__ void __launch_bounds__(256) k_xattn(const float* __restrict__ x) {
    const int b = blockIdx.z;
    const int jh = blockIdx.y;
    const int cbase = blockIdx.x * 16 + (threadIdx.x >> 5) * 2;
    const int tid = threadIdx.x;
    const int lane = tid & 31;

    __shared__ float4 attn_s[NH][256];  // one 1024-j chunk, 32 KB

    float acc[NH][2];
#pragma unroll
    for (int n = 0; n < NH; ++n) { acc[n][0] = 0.f; acc[n][1] = 0.f; }

    const float4* ap = (const float4*)(g_attn + (size_t)b * NH * TT);

    for (int chunk = 0; chunk < 2; ++chunk) {
        const int jq0 = jh * 512 + chunk * 256;  // float4 index of chunk start
        __syncthreads();
        for (int i = tid; i < NH * 256; i += 256)
            attn_s[i >> 8][i & 255] = ap[(i >> 8) * (TT / 4) + jq0 + (i & 255)];
        __syncthreads();

        const float4* xp = (const float4*)(x + (size_t)b * CC * TT) + jq0;
#pragma unroll
        for (int step = 0; step < 8; step += 4) {
            float4 xv[4][2];
            int qidx[4];
#pragma unroll
            for (int u = 0; u < 4; ++u) {
                qidx[u] = lane + (step + u) * 32;
#pragma unroll
                for (int cc = 0; cc < 2; ++cc)
                    xv[u][cc] = xp[(size_t)(cbase + cc) * (TT / 4) + qidx[u]];
            }
#pragma unroll
            for (int n = 0; n < NH; ++n) {
#pragma unroll
                for (int u = 0; u < 4; ++u) {
                    const float4 a = attn_s[n][qidx[u]];
#pragma unroll
                    for (int cc = 0; cc < 2; ++cc)
                        acc[n][cc] += a.x * xv[u][cc].x + a.y * xv[u][cc].y +
                                      a.z * xv[u][cc].z + a.w * xv[u][cc].w;
                }
            }
        }
    }

#pragma unroll
    for (int n = 0; n < NH; ++n)
#pragma unroll
        for (int cc = 0; cc < 2; ++cc) {
            float v = acc[n][cc];
#pragma unroll
            for (int o = 16; o; o >>= 1) v += __shfl_xor_sync(~0u, v, o);
            if (lane == 0) g_xp[jh][(size_t)(b * NH + n) * CC + cbase + cc] = v;
        }
}

// ---------------------------------------------------------------------------
// Kernel E: oh[nd] = Wkv_v[nd]·xattn[b,n] + bkv_v ; y = relu(oh@Wfc.T + bfc)
// grid = 32, 512 threads. Warp-per-row coalesced dots.
// ---------------------------------------------------------------------------
__global__ void __launch_bounds__(512) k_out(const float* __restrict__ Wkv,
                      const float* __restrict__ bkv,
                      const float* __restrict__ Wfc,
                      const float* __restrict__ bfc,
                      float* __restrict__ out) {
    const int b = blockIdx.x;
    const int tid = threadIdx.x, wid = tid >> 5, lane = tid & 31;
    __shared__ float xa[NH * CC];
    __shared__ float oh[DK];

    for (int i = tid; i < NH * CC; i += 512)
        xa[i] = g_xp[0][b * NH * CC + i] + g_xp[1][b * NH * CC + i];
    __syncthreads();

    for (int nd = wid; nd < DK; nd += 16) {
        const float4* wr = (const float4*)(Wkv + (size_t)(DK + nd) * CC);  // v rows
        const float4* xr = (const float4*)(xa + (nd >> 6) * CC);
        float s = 0.f;
#pragma unroll
        for (int i = 0; i < 2; ++i) {
            const float4 w = wr[lane + i * 32];
            const float4 v = xr[lane + i * 32];
            s += w.x * v.x + w.y * v.y + w.z * v.z + w.w * v.w;
        }
#pragma unroll
        for (int o = 16; o; o >>= 1) s += __shfl_xor_sync(~0u, s, o);
        if (!lane) oh[nd] = s + bkv[DK + nd];
    }
    __syncthreads();

    const float4* ov = (const float4*)oh;
    for (int o = wid; o < CC; o += 16) {
        const float4* wr = (const float4*)(Wfc + (size_t)o * DK);
        float s = 0.f;
#pragma unroll
        for (int i = 0; i < 4; ++i) {
            const float4 w = wr[lane + i * 32];
            const float4 v = ov[lane + i * 32];
            s += w.x * v.x + w.y * v.y + w.z * v.z + w.w * v.w;
        }
#pragma unroll
        for (int oo = 16; oo; oo >>= 1) s += __shfl_xor_sync(~0u, s, oo);
        if (!lane) out[b * CC + o] = fmaxf(s + bfc[o], 0.f);
    }
}

// ---------------------------------------------------------------------------
extern "C" void kernel_launch(void* const* d_in, const int* in_sizes, int n_in,
                              void* d_out, int out_size) {
    const float* x     = (const float*)d_in[0];  // (32,256,64,64)
    const float* query = (const float*)d_in[1];  // (32,256)
    const float* Wkv   = (const float*)d_in[2];  // (1024,256)
    const float* bkv   = (const float*)d_in[3];  // (1024)
    const float* Wq    = (const float*)d_in[4];  // (512,256)
    const float* bq    = (const float*)d_in[5];  // (512)
    const float* Wfc   = (const float*)d_in[6];  // (256,512)
    const float* bfc   = (const float*)d_in[7];  // (256)
    float* out = (float*)d_out;                  // (32,256)

    k_prep<<<dim3(NH, BB), 256>>>(query, Wq, bq, Wkv);
    k_logits<<<dim3(TT / 512, 4, BB), 128>>>(x);
    k_softmax<<<BB * NH, 256>>>();
    k_xattn<<<dim3(CC / 16, 2, BB), 256>>>(x);
    k_out<<<BB, 512>>>(Wkv, bkv, Wfc, bfc, out);
}

// round 6
// speedup vs baseline: 1.3742x; 1.3742x over previous
#include <cuda_runtime.h>

#define BB 32
#define CC 256
#define TT 4096
#define NH 8
#define DH 64
#define DK 512   // NH*DH

// Scratch (allocation-free per harness rules)
__device__ float g_qW[BB * NH * CC];        // scale-folded q @ Wkv_k
__device__ float g_pl[4][BB * NH * TT];     // partial logits, 4 c-quarters
__device__ float g_attn[BB * NH * TT];      // softmax output
__device__ float g_xp[2][BB * NH * CC];     // xattn partials, 2 j-halves
__device__ float g_oh[BB * DK];             // v-projection intermediate

// ---------------------------------------------------------------------------
// Kernel A: per (n,b): q[n,:] = query@Wq.T + bq ; qW[b,n,c] = scale * q·Wkv_k[:,c]
// grid = (8 n, 32 b), 256 threads
// ---------------------------------------------------------------------------
__global__ void k_prep(const float* __restrict__ query,
                       const float* __restrict__ Wq,
                       const float* __restrict__ bq,
                       const float* __restrict__ Wkv) {
    const int n = blockIdx.x, b = blockIdx.y;
    const int tid = threadIdx.x, wid = tid >> 5, lane = tid & 31;
    __shared__ float qin[CC];
    __shared__ float qs[DH];

    qin[tid] = query[b * CC + tid];
    __syncthreads();

    const float4* qv = (const float4*)qin;
    for (int d = wid; d < DH; d += 8) {
        const float4* wr = (const float4*)(Wq + (size_t)(n * DH + d) * CC);
        float s = 0.f;
#pragma unroll
        for (int i = 0; i < 2; ++i) {
            const float4 w = wr[lane + i * 32];
            const float4 q4 = qv[lane + i * 32];
            s += w.x * q4.x + w.y * q4.y + w.z * q4.z + w.w * q4.w;
        }
#pragma unroll
        for (int o = 16; o; o >>= 1) s += __shfl_xor_sync(~0u, s, o);
        if (!lane) qs[d] = s + bq[n * DH + d];
    }
    __syncthreads();

    const float* wbase = Wkv + (size_t)(n * DH) * CC + tid;
    float s = 0.f;
#pragma unroll 8
    for (int d = 0; d < DH; ++d) s += qs[d] * wbase[(size_t)d * CC];
    g_qW[(b * NH + n) * CC + tid] = s * 0.125f;  // 1/sqrt(64)
}

// ---------------------------------------------------------------------------
// Kernel B: partial logits, c split in quarters across blockIdx.y.
// grid = (4 j-tiles of 1024, 4 c-quarters, 32 b), 256 threads.  (R4 exact)
// ---------------------------------------------------------------------------
__global__ void __launch_bounds__(256) k_logits(const float* __restrict__ x) {
    const int b = blockIdx.z;
    const int cq = blockIdx.y;                       // c quarter
    const int jq = blockIdx.x * 256 + threadIdx.x;   // float4 index into j

    __shared__ float4 qwT[64][2];                    // [c][n-quad], 512 floats
    for (int i = threadIdx.x; i < 64 * NH; i += 256) {
        const int c = i >> 3, n = i & 7;
        ((float*)&qwT[c][0])[n] = g_qW[(b * NH + n) * CC + cq * 64 + c];
    }
    __syncthreads();

    float4 acc[NH];
#pragma unroll
    for (int n = 0; n < NH; ++n) acc[n] = make_float4(0.f, 0.f, 0.f, 0.f);

    const float4* xp = (const float4*)(x + ((size_t)b * CC + cq * 64) * TT) + jq;
#pragma unroll 8
    for (int c = 0; c < 64; ++c) {
        const float4 xv = __ldcs(&xp[(size_t)c * (TT / 4)]);
        const float4 w0 = qwT[c][0];
        const float4 w1 = qwT[c][1];
        acc[0].x += w0.x * xv.x; acc[0].y += w0.x * xv.y; acc[0].z += w0.x * xv.z; acc[0].w += w0.x * xv.w;
        acc[1].x += w0.y * xv.x; acc[1].y += w0.y * xv.y; acc[1].z += w0.y * xv.z; acc[1].w += w0.y * xv.w;
        acc[2].x += w0.z * xv.x; acc[2].y += w0.z * xv.y; acc[2].z += w0.z * xv.z; acc[2].w += w0.z * xv.w;
        acc[3].x += w0.w * xv.x; acc[3].y += w0.w * xv.y; acc[3].z += w0.w * xv.z; acc[3].w += w0.w * xv.w;
        acc[4].x += w1.x * xv.x; acc[4].y += w1.x * xv.y; acc[4].z += w1.x * xv.z; acc[4].w += w1.x * xv.w;
        acc[5].x += w1.y * xv.x; acc[5].y += w1.y * xv.y; acc[5].z += w1.y * xv.z; acc[5].w += w1.y * xv.w;
        acc[6].x += w1.z * xv.x; acc[6].y += w1.z * xv.y; acc[6].z += w1.z * xv.z; acc[6].w += w1.z * xv.w;
        acc[7].x += w1.w * xv.x; acc[7].y += w1.w * xv.y; acc[7].z += w1.w * xv.z; acc[7].w += w1.w * xv.w;
    }

#pragma unroll
    for (int n = 0; n < NH; ++n)
        ((float4*)(g_pl[cq] + (size_t)(b * NH + n) * TT))[jq] = acc[n];
}

// ---------------------------------------------------------------------------
// Kernel C: logits = sum of 4 partials, softmax over j=4096.
// grid = 256 rows, 256 threads
// ---------------------------------------------------------------------------
__global__ void k_softmax() {
    const int row = blockIdx.x;
    const int tid = threadIdx.x;
    float4* pa = (float4*)(g_attn + (size_t)row * TT);

    float4 v[4];
#pragma unroll
    for (int i = 0; i < 4; ++i) {
        float4 a = ((const float4*)(g_pl[0] + (size_t)row * TT))[tid + i * 256];
#pragma unroll
        for (int p = 1; p < 4; ++p) {
            const float4 c = ((const float4*)(g_pl[p] + (size_t)row * TT))[tid + i * 256];
            a.x += c.x; a.y += c.y; a.z += c.z; a.w += c.w;
        }
        v[i] = a;
    }

    float m = -1e30f;
#pragma unroll
    for (int i = 0; i < 4; ++i)
        m = fmaxf(m, fmaxf(fmaxf(v[i].x, v[i].y), fmaxf(v[i].z, v[i].w)));

    __shared__ float red[8];
#pragma unroll
    for (int o = 16; o; o >>= 1) m = fmaxf(m, __shfl_xor_sync(~0u, m, o));
    if ((tid & 31) == 0) red[tid >> 5] = m;
    __syncthreads();
    m = red[0];
#pragma unroll
    for (int i = 1; i < 8; ++i) m = fmaxf(m, red[i]);
    __syncthreads();

    float s = 0.f;
#pragma unroll
    for (int i = 0; i < 4; ++i) {
        v[i].x = __expf(v[i].x - m); v[i].y = __expf(v[i].y - m);
        v[i].z = __expf(v[i].z - m); v[i].w = __expf(v[i].w - m);
        s += v[i].x + v[i].y + v[i].z + v[i].w;
    }
#pragma unroll
    for (int o = 16; o; o >>= 1) s += __shfl_xor_sync(~0u, s, o);
    if ((tid & 31) == 0) red[tid >> 5] = s;
    __syncthreads();
    s = red[0];
#pragma unroll
    for (int i = 1; i < 8; ++i) s += red[i];

    const float inv = 1.f / s;
#pragma unroll
    for (int i = 0; i < 4; ++i) {
        v[i].x *= inv; v[i].y *= inv; v[i].z *= inv; v[i].w *= inv;
        pa[tid + i * 256] = v[i];
    }
}

// ---------------------------------------------------------------------------
// Kernel D: xattn partial over j-half. grid = (8 c-tiles of 32, 2 jh, 32 b),
// 256 threads = 8 warps, warp owns 4 c. Unroll 4: 16 LDG.128 in flight.
// ---------------------------------------------------------------------------
__global__ void __launch_bounds__(256, 2) k_xattn(const float* __restrict__ x) {
    const int b = blockIdx.z;
    const int jh = blockIdx.y;
    const int cbase = blockIdx.x * 32 + (threadIdx.x >> 5) * 4;
    const int tid = threadIdx.x;
    const int lane = tid & 31;

    __shared__ float4 attn_s[NH][256];  // one 1024-j chunk, 32 KB

    float acc[NH][4];
#pragma unroll
    for (int n = 0; n < NH; ++n)
#pragma unroll
        for (int cc = 0; cc < 4; ++cc) acc[n][cc] = 0.f;

    const float4* ap = (const float4*)(g_attn + (size_t)b * NH * TT);

    for (int chunk = 0; chunk < 2; ++chunk) {
        const int jq0 = jh * 512 + chunk * 256;  // float4 index of chunk start
        __syncthreads();
        for (int i = tid; i < NH * 256; i += 256)
            attn_s[i >> 8][i & 255] = ap[(i >> 8) * (TT / 4) + jq0 + (i & 255)];
        __syncthreads();

        const float4* xp = (const float4*)(x + (size_t)b * CC * TT) + jq0;
#pragma unroll
        for (int step = 0; step < 8; step += 4) {
            // Batch all 16 loads first: maximize outstanding LDG.128
            float4 xv[4][4];
#pragma unroll
            for (int u = 0; u < 4; ++u) {
                const int q = lane + (step + u) * 32;
#pragma unroll
                for (int cc = 0; cc < 4; ++cc)
                    xv[u][cc] = __ldcs(&xp[(size_t)(cbase + cc) * (TT / 4) + q]);
            }
#pragma unroll
            for (int u = 0; u < 4; ++u) {
                const int q = lane + (step + u) * 32;
#pragma unroll
                for (int n = 0; n < NH; ++n) {
                    const float4 a = attn_s[n][q];
#pragma unroll
                    for (int cc = 0; cc < 4; ++cc)
                        acc[n][cc] += a.x * xv[u][cc].x + a.y * xv[u][cc].y +
                                      a.z * xv[u][cc].z + a.w * xv[u][cc].w;
                }
            }
        }
    }

#pragma unroll
    for (int n = 0; n < NH; ++n)
#pragma unroll
        for (int cc = 0; cc < 4; ++cc) {
            float v = acc[n][cc];
#pragma unroll
            for (int o = 16; o; o >>= 1) v += __shfl_xor_sync(~0u, v, o);
            if (lane == 0) g_xp[jh][(size_t)(b * NH + n) * CC + cbase + cc] = v;
        }
}

// ---------------------------------------------------------------------------
// Kernel E1: oh[b,nd] = Wkv_v[nd]·xattn[b,n] + bkv_v[nd]
// grid = (32 b, 4 nd-tiles of 128), 128 threads = 4 warps, warp per row
// ---------------------------------------------------------------------------
__global__ void __launch_bounds__(128) k_out1(const float* __restrict__ Wkv,
                                              const float* __restrict__ bkv) {
    const int b = blockIdx.x, tile = blockIdx.y;
    const int tid = threadIdx.x, wid = tid >> 5, lane = tid & 31;
    __shared__ float xa[2 * CC];  // two heads for this nd-tile

    for (int i = tid; i < 2 * CC; i += 128) {
        const int gi = b * NH * CC + tile * 2 * CC + i;
        xa[i] = g_xp[0][gi] + g_xp[1][gi];
    }
    __syncthreads();

    for (int ndl = wid; ndl < 128; ndl += 4) {
        const int nd = tile * 128 + ndl;
        const float4* wr = (const float4*)(Wkv + (size_t)(DK + nd) * CC);
        const float4* xr = (const float4*)(xa + (ndl >> 6) * CC);
        float s = 0.f;
#pragma unroll
        for (int i = 0; i < 2; ++i) {
            const float4 w = wr[lane + i * 32];
            const float4 v = xr[lane + i * 32];
            s += w.x * v.x + w.y * v.y + w.z * v.z + w.w * v.w;
        }
#pragma unroll
        for (int o = 16; o; o >>= 1) s += __shfl_xor_sync(~0u, s, o);
        if (!lane) g_oh[b * DK + nd] = s + bkv[DK + nd];
    }
}

// ---------------------------------------------------------------------------
// Kernel E2: y[b,o] = relu(oh[b]·Wfc[o] + bfc[o])
// grid = (32 b, 2 o-halves of 128), 256 threads = 8 warps, warp per row
// ---------------------------------------------------------------------------
__global__ void __launch_bounds__(256) k_out2(const float* __restrict__ Wfc,
                                              const float* __restrict__ bfc,
                                              float* __restrict__ out) {
    const int b = blockIdx.x, half = blockIdx.y;
    const int tid = threadIdx.x, wid = tid >> 5, lane = tid & 31;
    __shared__ float oh[DK];

    for (int i = tid; i < DK; i += 256) oh[i] = g_oh[b * DK + i];
    __syncthreads();

    const float4* ov = (const float4*)oh;
    for (int ol = wid; ol < 128; ol += 8) {
        const int o = half * 128 + ol;
        const float4* wr = (const float4*)(Wfc + (size_t)o * DK);
        float s = 0.f;
#pragma unroll
        for (int i = 0; i < 4; ++i) {
            const float4 w = wr[lane + i * 32];
            const float4 v = ov[lane + i * 32];
            s += w.x * v.x + w.y * v.y + w.z * v.z + w.w * v.w;
        }
#pragma unroll
        for (int oo = 16; oo; oo >>= 1) s += __shfl_xor_sync(~0u, s, oo);
        if (!lane) out[b * CC + o] = fmaxf(s + bfc[o], 0.f);
    }
}

// ---------------------------------------------------------------------------
extern "C" void kernel_launch(void* const* d_in, const int* in_sizes, int n_in,
                              void* d_out, int out_size) {
    const float* x     = (const float*)d_in[0];  // (32,256,64,64)
    const float* query = (const float*)d_in[1];  // (32,256)
    const float* Wkv   = (const float*)d_in[2];  // (1024,256)
    const float* bkv   = (const float*)d_in[3];  // (1024)
    const float* Wq    = (const float*)d_in[4];  // (512,256)
    const float* bq    = (const float*)d_in[5];  // (512)
    const float* Wfc   = (const float*)d_in[6];  // (256,512)
    const float* bfc   = (const float*)d_in[7];  // (256)
    float* out = (float*)d_out;                  // (32,256)

    k_prep<<<dim3(NH, BB), 256>>>(query, Wq, bq, Wkv);
    k_logits<<<dim3(TT / 1024, 4, BB), 256>>>(x);
    k_softmax<<<BB * NH, 256>>>();
    k_xattn<<<dim3(CC / 32, 2, BB), 256>>>(x);
    k_out1<<<dim3(BB, 4), 128>>>(Wkv, bkv);
    k_out2<<<dim3(BB, 2), 256>>>(Wfc, bfc, out);
}